// round 14
// baseline (speedup 1.0000x reference)
#include <cuda_runtime.h>
#include <math.h>

#define BB 16
#define NN 16384
#define NCHUNK (NN / 32)        // 512
#define NGROUP (NCHUNK / 4)     // 128 groups of 4 chunks

// ---------------------------------------------------------------------------
// Single fused kernel. One block = 5 warps per batch row (160 threads).
//   wid 4 (compute): recurrence with register/shfl handling of chunk-(c-1)
//     taps and pre-issued ring gathers for older taps:
//       tap j of chunk c lies in chunk c-1  <=>  mm >= 65+j  (mm = lane-zc+97)
//       - c-1 taps: __shfl_sync of the previous chunk's acc register
//       - taps <= c-2: SMEM ring gather, issued off the critical chain
//         (G0,G1 after the group barrier; G2,G3 after one mid-group syncwarp)
//     Ring: 256 + 7-slot mirror, pre-zeroed => zero initial state free.
//     Publication: group-start __syncthreads publishes chunks <= 4g-1;
//     mid-group __syncwarp publishes chunks <= 4g+1 (needed by G2,G3).
//   wids 0..3 (helpers): helper warp w owns chunk w of every group; computes
//     coefficients for group g+2 (inputs LDG'd at g-1) into SMEM stages;
//     wid 1 copies group g-1's ring slots to gmem; __syncthreads per group.
// ---------------------------------------------------------------------------
struct SmemCoef {
    float4 A[16][32];
    float4 B[16][32];
    int    I[16][32];
};

__device__ __forceinline__ void coef_one(float f0v, float xv, float gg, float pp,
                                         int n, float4& A, float4& B, int& meta)
{
    float g  = 0.99f * gg;
    float b0 = g * (1.0f - pp);
    float a1 = g * pp;
    float f0c = f0v - a1 / (b0 + a1 + 1e-7f);

    int   zc    = (int)floorf(f0c) - 2;     // in [37, 97]
    float alpha = f0c - (float)zc;          // in [2, 3)

    float u0 = alpha;
    float u1 = alpha - 1.0f;
    float u2 = alpha - 2.0f;
    float u3 = alpha - 3.0f;
    float u4 = alpha - 4.0f;
    float u5 = alpha - 5.0f;

    float pre1 = u0;
    float pre2 = pre1 * u1;
    float pre3 = pre2 * u2;
    float pre4 = pre3 * u3;
    float pre5 = pre4 * u4;
    float suf4 = u5;
    float suf3 = suf4 * u4;
    float suf2 = suf3 * u3;
    float suf1 = suf2 * u2;
    float suf0 = suf1 * u1;

    float w0 = suf0        * (-1.0f / 120.0f);
    float w1 = pre1 * suf1 * ( 1.0f /  24.0f);
    float w2 = pre2 * suf2 * (-1.0f /  12.0f);
    float w3 = pre3 * suf3 * ( 1.0f /  12.0f);
    float w4 = pre4 * suf4 * (-1.0f /  24.0f);
    float w5 = pre5        * ( 1.0f / 120.0f);

    A = make_float4(b0 * w0,
                    fmaf(b0, w1, a1 * w0),
                    fmaf(b0, w2, a1 * w1),
                    fmaf(b0, w3, a1 * w2));
    B = make_float4(fmaf(b0, w4, a1 * w3),
                    fmaf(b0, w5, a1 * w4),
                    a1 * w5,
                    xv);
    int base = n - zc;
    int lo   = (base - 6) & 255;            // ring slot of window start
    int mm   = (n & 31) - zc + 97;          // in [0, 91]
    meta = lo | (mm << 8);
}

// 7-tap ring gather (off-chain; stale entries under shfl-selected taps are
// discarded by the selects in chunk_mix).
__device__ __forceinline__ void gather7(const float* ring, int lo, float* G)
{
    const float* w = ring + lo;             // [lo, lo+6] never wraps (mirror)
#pragma unroll
    for (int k = 0; k < 7; k++) G[k] = w[k];
}

// One chunk: c-1 taps via shfl of prev chunk's acc; older taps from G.
__device__ __forceinline__ float chunk_mix(float4 A, float4 B, int mm, int r,
                                           float prev, const float* G)
{
    float h0 = __shfl_sync(0xffffffffu, prev, r    );
    float h1 = __shfl_sync(0xffffffffu, prev, r - 1);
    float h2 = __shfl_sync(0xffffffffu, prev, r - 2);
    float h3 = __shfl_sync(0xffffffffu, prev, r - 3);
    float h4 = __shfl_sync(0xffffffffu, prev, r - 4);
    float h5 = __shfl_sync(0xffffffffu, prev, r - 5);
    float h6 = __shfl_sync(0xffffffffu, prev, r - 6);

    float v0 = (mm >= 65) ? h0 : G[6];
    float v1 = (mm >= 66) ? h1 : G[5];
    float v2 = (mm >= 67) ? h2 : G[4];
    float v3 = (mm >= 68) ? h3 : G[3];
    float v4 = (mm >= 69) ? h4 : G[2];
    float v5 = (mm >= 70) ? h5 : G[1];
    float v6 = (mm >= 71) ? h6 : G[0];

    float t0 = fmaf(A.x, v0, B.w);          // x[n] + blk0*v0
    float t1 = fmaf(A.z, v2, A.y * v1);
    float t2 = fmaf(B.x, v4, A.w * v3);
    float t3 = fmaf(B.z, v6, B.y * v5);
    return (t0 + t1) + (t2 + t3);
}

__global__ void __launch_bounds__(160, 1)
lpc_kernel(const float* __restrict__ f0,
           const float* __restrict__ x,
           const float* __restrict__ lb,
           float* __restrict__ out)
{
    __shared__ SmemCoef sc;
    __shared__ float ring[264];

    const int b    = blockIdx.x;
    const int tid  = threadIdx.x;
    const int wid  = tid >> 5;
    const int lane = tid & 31;
    const float*  __restrict__ f0r = f0 + b * NN;
    const float*  __restrict__ xr  = x  + b * NN;
    const float2* __restrict__ lbr = reinterpret_cast<const float2*>(lb) + b * NN;
    float* __restrict__ outr = out + b * NN;

    float  cf0, cx;
    float2 cgp;
    int h = 0;

    if (wid == 4) {
        // compute warp: zero the ring (zero initial state via wrap mapping)
#pragma unroll
        for (int k = 0; k < 8; k++) ring[lane + 32 * k] = 0.0f;
        if (lane < 8) ring[256 + lane] = 0.0f;
    } else {
        h = wid * 32 + lane;              // sample offset within a group

        // prologue: LDG inputs for groups 0,1,2
        float  f0_0 = f0r[h],       x_0 = xr[h];
        float2 gp_0 = lbr[h];
        float  f0_1 = f0r[128 + h], x_1 = xr[128 + h];
        float2 gp_1 = lbr[128 + h];
        cf0 = f0r[256 + h]; cx = xr[256 + h]; cgp = lbr[256 + h];

        float4 A, B; int m;
        coef_one(f0_0, x_0, gp_0.x, gp_0.y, h, A, B, m);           // group 0
        sc.A[wid][lane] = A; sc.B[wid][lane] = B; sc.I[wid][lane] = m;
        coef_one(f0_1, x_1, gp_1.x, gp_1.y, 128 + h, A, B, m);     // group 1
        sc.A[4 + wid][lane] = A; sc.B[4 + wid][lane] = B; sc.I[4 + wid][lane] = m;
    }
    __syncthreads();

    if (wid == 4) {
        // ---------------- compute warp ----------------
        const bool lane_lt7 = lane < 7;
        float yPrev = 0.0f;                 // chunk -1 values (zero state)

        float4 A0 = sc.A[0][lane], B0 = sc.B[0][lane];
        float4 A1 = sc.A[1][lane], B1 = sc.B[1][lane];
        float4 A2 = sc.A[2][lane], B2 = sc.B[2][lane];
        float4 A3 = sc.A[3][lane], B3 = sc.B[3][lane];
        int I0 = sc.I[0][lane];
        int I1 = sc.I[1][lane];
        int I2 = sc.I[2][lane];
        int I3 = sc.I[3][lane];

        float G0[7], G1[7], G2[7], G3[7];

        for (int g = 0; g < NGROUP; g++) {
            const int wb = (g & 1) * 128;           // ring write base
            const bool mir = ((g & 1) == 0) && lane_lt7;   // chunk 4g = 0 mod 8

            const int lo0 = I0 & 255, mm0 = I0 >> 8;
            const int lo1 = I1 & 255, mm1 = I1 >> 8;
            const int lo2 = I2 & 255, mm2 = I2 >> 8;
            const int lo3 = I3 & 255, mm3 = I3 >> 8;

            // gathers for chunks 0,1: read chunks <= 4g-1, published by the
            // group-start barrier
            gather7(ring, lo0, G0);
            gather7(ring, lo1, G1);

            float acc0 = chunk_mix(A0, B0, mm0, lo0 + 6, yPrev, G0);
            ring[wb + lane] = acc0;
            if (mir) ring[256 + lane] = acc0;

            float acc1 = chunk_mix(A1, B1, mm1, lo1 + 6, acc0, G1);
            ring[wb + 32 + lane] = acc1;

            __syncwarp();                   // publish chunks 4g, 4g+1

            // gathers for chunks 2,3: read chunks <= 4g+1 (just published)
            gather7(ring, lo2, G2);
            gather7(ring, lo3, G3);

            float acc2 = chunk_mix(A2, B2, mm2, lo2 + 6, acc1, G2);
            ring[wb + 64 + lane] = acc2;

            float acc3 = chunk_mix(A3, B3, mm3, lo3 + 6, acc2, G3);
            ring[wb + 96 + lane] = acc3;
            yPrev = acc3;

            // preload group g+1 coefficients (stage written >=1 barrier ago)
            const int st = ((g + 1) & 3) * 4;
            A0 = sc.A[st + 0][lane]; B0 = sc.B[st + 0][lane];
            A1 = sc.A[st + 1][lane]; B1 = sc.B[st + 1][lane];
            A2 = sc.A[st + 2][lane]; B2 = sc.B[st + 2][lane];
            A3 = sc.A[st + 3][lane]; B3 = sc.B[st + 3][lane];
            I0 = sc.I[st + 0][lane];
            I1 = sc.I[st + 1][lane];
            I2 = sc.I[st + 2][lane];
            I3 = sc.I[st + 3][lane];

            __syncthreads();                // group boundary
        }
    } else {
        // ---------------- helper warps (wid 0..3) ----------------
        for (int g = 0; g < NGROUP; g++) {
            if (g + 2 < NGROUP) {                   // coefs for group g+2
                const int st = ((g + 2) & 3) * 4 + wid;
                float4 A, B; int m;
                coef_one(cf0, cx, cgp.x, cgp.y, (g + 2) * 128 + h, A, B, m);
                sc.A[st][lane] = A; sc.B[st][lane] = B; sc.I[st][lane] = m;
            }
            if (g + 3 < NGROUP) {                   // LDG inputs for group g+3
                const int s = (g + 3) * 128 + h;
                cf0 = f0r[s]; cx = xr[s]; cgp = lbr[s];
            }
            if (wid == 1 && g >= 1) {               // copy group g-1 -> gmem
                const int rb = ((g - 1) & 1) * 128;
                float* o = outr + (g - 1) * 128 + lane;
#pragma unroll
                for (int k = 0; k < 4; k++)
                    o[k * 32] = ring[rb + k * 32 + lane];
            }
            __syncthreads();
        }
        // final group's output (last __syncthreads drained compute's STS)
        if (wid == 1) {
            const int rb = ((NGROUP - 1) & 1) * 128;
            float* o = outr + (NGROUP - 1) * 128 + lane;
#pragma unroll
            for (int k = 0; k < 4; k++)
                o[k * 32] = ring[rb + k * 32 + lane];
        }
    }
}

// ---------------------------------------------------------------------------
// Inputs (metadata order): f0 [B,N] f32, x [B,N] f32, l_b [B,N,2] f32, K int32
// Output: y [B,N] f32
// ---------------------------------------------------------------------------
extern "C" void kernel_launch(void* const* d_in, const int* in_sizes, int n_in,
                              void* d_out, int out_size)
{
    const float* f0 = (const float*)d_in[0];
    const float* x  = (const float*)d_in[1];
    const float* lb = (const float*)d_in[2];
    float* out = (float*)d_out;

    lpc_kernel<<<BB, 160>>>(f0, x, lb, out);
}